// round 3
// baseline (speedup 1.0000x reference)
#include <cuda_runtime.h>
#include <cuda_bf16.h>

// Problem shape (fixed by reference): B=4, A=9, H=256, W=256, C=9, F=64
#define B_ 4
#define A_ 9
#define H_ 256
#define W_ 256
#define C_ 9
#define F_ 64

// Scratch (device globals — no allocation allowed in kernel_launch)
__device__ float g_m[B_ * H_ * W_];        // mean over (A, C) of lfi   [b,h,w]
__device__ float g_hv[B_ * W_ * F_];       // mean over H of f_maps     [b,w,f]
__device__ float g_scale[B_ * W_ * F_];    // hv / max_w hv             [b,w,f]

// ---------------------------------------------------------------------------
// Kernel A: m[b,h,w] = mean_{a,c} lfi[b,a,h,w,c]
// One thread per (b,h,w). For each a, the 9 c-values are contiguous; a warp
// covering w..w+31 touches a contiguous 1152-byte span -> fully coalesced,
// every 32B sector consumed. 9 independent load-streams visible after unroll
// gives ample MLP against ~577cyc DRAM latency.
// ---------------------------------------------------------------------------
__global__ void reduce_lfi_kernel(const float* __restrict__ lfi) {
    int idx = blockIdx.x * blockDim.x + threadIdx.x;   // 0 .. B*H*W-1
    if (idx >= B_ * H_ * W_) return;
    int w = idx & (W_ - 1);
    int h = (idx >> 8) & (H_ - 1);
    int b = idx >> 16;

    float s0 = 0.f, s1 = 0.f, s2 = 0.f;
#pragma unroll
    for (int a = 0; a < A_; a++) {
        const float* p = lfi + ((((size_t)b * A_ + a) * H_ + h) * W_ + w) * C_;
        s0 += p[0] + p[3] + p[6];
        s1 += p[1] + p[4] + p[7];
        s2 += p[2] + p[5] + p[8];
    }
    g_m[idx] = (s0 + s1 + s2) * (1.0f / (A_ * C_));
}

// ---------------------------------------------------------------------------
// Kernel B: hv[b,w,f] = mean_h f_maps[b,h,w,f]
// One block per (b,w); 256 threads = 64 f-lanes x 4 h-quarters.
// Each h-step, a warp reads 128B contiguous (consecutive f). Shared combine.
// 1024 blocks -> full chip; 64 outstanding loads per thread.
// ---------------------------------------------------------------------------
__global__ void colmean_fmaps_kernel(const float* __restrict__ fm) {
    __shared__ float sm[256];
    int bid = blockIdx.x;                // 0 .. B*W-1
    if (bid >= B_ * W_) return;
    int b = bid >> 8;
    int w = bid & (W_ - 1);
    int tid = threadIdx.x;
    int f  = tid & (F_ - 1);
    int hq = tid >> 6;                   // 0..3

    const float* p = fm + (size_t)b * H_ * W_ * F_ + (size_t)w * F_ + f;
    float s = 0.f;
    int h0 = hq * 64;
#pragma unroll 8
    for (int h = h0; h < h0 + 64; h++) {
        s += p[(size_t)h * (W_ * F_)];
    }
    sm[tid] = s;
    __syncthreads();
    if (tid < 64) {
        float total = sm[tid] + sm[tid + 64] + sm[tid + 128] + sm[tid + 192];
        g_hv[(b * W_ + w) * F_ + tid] = total * (1.0f / H_);
    }
}

// ---------------------------------------------------------------------------
// Kernel C: scale[b,w,f] = hv[b,w,f] / max_w' hv[b,w',f]
// One block per (b,f); 256 threads over w. Tiny (64KB), latency-irrelevant.
// ---------------------------------------------------------------------------
__global__ void normalize_kernel() {
    __shared__ float sm[256];
    int bid = blockIdx.x;                // 0 .. B*F-1
    if (bid >= B_ * F_) return;
    int b = bid >> 6;
    int f = bid & (F_ - 1);
    int w = threadIdx.x;

    float v = g_hv[(b * W_ + w) * F_ + f];
    sm[w] = v;
    __syncthreads();
#pragma unroll
    for (int off = 128; off > 0; off >>= 1) {
        if (w < off) sm[w] = fmaxf(sm[w], sm[w + off]);
        __syncthreads();
    }
    float inv = 1.0f / sm[0];
    g_scale[(b * W_ + w) * F_ + f] = v * inv;
}

// ---------------------------------------------------------------------------
// Kernel D: out[b,h,w,f] = m[b,h,w] * scale[b,h,f]   (note: h indexes scale's
// w-dimension, per the reference transpose). float4 stores (STG.128);
// m and scale reads are tiny and L1/L2-resident.
// ---------------------------------------------------------------------------
__global__ void finalize_kernel(float4* __restrict__ out) {
    int idx = blockIdx.x * blockDim.x + threadIdx.x;   // 0 .. B*H*W*F/4 - 1
    if (idx >= B_ * H_ * W_ * F_ / 4) return;
    int f4 = idx & 15;                  // which float4 along F
    int w = (idx >> 4) & (W_ - 1);
    int h = (idx >> 12) & (H_ - 1);
    int b = idx >> 20;

    float mv = g_m[(b * H_ + h) * W_ + w];
    const float4* scp = reinterpret_cast<const float4*>(g_scale);
    float4 sc = scp[(b * W_ + h) * (F_ / 4) + f4];
    float4 o;
    o.x = mv * sc.x;
    o.y = mv * sc.y;
    o.z = mv * sc.z;
    o.w = mv * sc.w;
    out[idx] = o;
}

extern "C" void kernel_launch(void* const* d_in, const int* in_sizes, int n_in,
                              void* d_out, int out_size) {
    const float* lfi = (const float*)d_in[0];   // [4,9,256,256,9]
    const float* fm  = (const float*)d_in[1];   // [4,256,256,64]
    float4* out = (float4*)d_out;               // [4,256,256,64]

    // A: 262144 threads
    reduce_lfi_kernel<<<(B_ * H_ * W_) / 256, 256>>>(lfi);
    // B: one block per (b,w)
    colmean_fmaps_kernel<<<B_ * W_, 256>>>(fm);
    // C: one block per (b,f)
    normalize_kernel<<<B_ * F_, 256>>>();
    // D: 4194304 threads (float4 granularity)
    finalize_kernel<<<(B_ * H_ * W_ * F_ / 4) / 256, 256>>>(out);
}

// round 4
// speedup vs baseline: 1.1276x; 1.1276x over previous
#include <cuda_runtime.h>
#include <cuda_bf16.h>

// Problem shape (fixed by reference): B=4, A=9, H=256, W=256, C=9, F=64
#define B_ 4
#define A_ 9
#define H_ 256
#define W_ 256
#define C_ 9
#define F_ 64

// Scratch (device globals — no allocation allowed in kernel_launch)
__device__ float g_hv[B_ * W_ * F_];       // mean over H of f_maps     [b,w,f]
__device__ float g_scale[B_ * W_ * F_];    // hv / max_w hv             [b,w,f]

// ---------------------------------------------------------------------------
// Kernel B: hv[b,w,f] = mean_h f_maps[b,h,w,f]
// One block per (b,w); 256 threads = 64 f-lanes x 4 h-quarters.
// Each h-step, a warp reads 128B contiguous (consecutive f). Shared combine.
// ---------------------------------------------------------------------------
__global__ void colmean_fmaps_kernel(const float* __restrict__ fm) {
    __shared__ float sm[256];
    int bid = blockIdx.x;                // 0 .. B*W-1
    int b = bid >> 8;
    int w = bid & (W_ - 1);
    int tid = threadIdx.x;
    int f  = tid & (F_ - 1);
    int hq = tid >> 6;                   // 0..3

    const float* p = fm + (size_t)b * H_ * W_ * F_ + (size_t)w * F_ + f;
    float s = 0.f;
    int h0 = hq * 64;
#pragma unroll 8
    for (int h = h0; h < h0 + 64; h++) {
        s += p[(size_t)h * (W_ * F_)];
    }
    sm[tid] = s;
    __syncthreads();
    if (tid < 64) {
        float total = sm[tid] + sm[tid + 64] + sm[tid + 128] + sm[tid + 192];
        g_hv[(b * W_ + w) * F_ + tid] = total * (1.0f / H_);
    }
}

// ---------------------------------------------------------------------------
// Kernel C: scale[b,w,f] = hv[b,w,f] / max_w' hv[b,w',f]
// One block per (b,f); 256 threads over w. Tiny, latency-irrelevant.
// ---------------------------------------------------------------------------
__global__ void normalize_kernel() {
    __shared__ float sm[256];
    int bid = blockIdx.x;                // 0 .. B*F-1
    int b = bid >> 6;
    int f = bid & (F_ - 1);
    int w = threadIdx.x;

    float v = g_hv[(b * W_ + w) * F_ + f];
    sm[w] = v;
    __syncthreads();
#pragma unroll
    for (int off = 128; off > 0; off >>= 1) {
        if (w < off) sm[w] = fmaxf(sm[w], sm[w + off]);
        __syncthreads();
    }
    float inv = 1.0f / sm[0];
    g_scale[(b * W_ + w) * F_ + f] = v * inv;
}

// ---------------------------------------------------------------------------
// Fused A+D: one block per (b,h).
//   Phase 1: thread tid computes m[w=tid] = mean_{a,c} lfi[b,a,h,w,c]
//            (81 coalesced scalar loads; warp spans 1152B contiguous per a).
//            Also threads 0..63 stage scale[b,h,:] (256B) into shared.
//   Phase 2: write out[b,h,:,:] = 64KB contiguous row as 4096 float4s,
//            16 independent STG.128 per thread, all operands from shared.
// Overlaps lfi DRAM reads (phase 1 of some blocks) with out writes (phase 2
// of other blocks) chip-wide.
// ---------------------------------------------------------------------------
__global__ void fused_m_out_kernel(const float* __restrict__ lfi,
                                   float4* __restrict__ out) {
    __shared__ float sm_m[W_];           // 256 floats: m[b,h,w]
    __shared__ float4 sm_s[F_ / 4];      // 64 floats:  scale[b,h,f]

    int bid = blockIdx.x;                // 0 .. B*H-1
    int b = bid >> 8;
    int h = bid & (H_ - 1);
    int tid = threadIdx.x;               // 0..255 == w

    // stage scale row (h indexes scale's w-dimension per reference transpose)
    if (tid < F_ / 4) {
        sm_s[tid] = reinterpret_cast<const float4*>(g_scale)[(b * W_ + h) * (F_ / 4) + tid];
    }

    // phase 1: m for w = tid
    {
        int w = tid;
        float s0 = 0.f, s1 = 0.f, s2 = 0.f;
#pragma unroll
        for (int a = 0; a < A_; a++) {
            const float* p = lfi + ((((size_t)b * A_ + a) * H_ + h) * W_ + w) * C_;
            s0 += p[0] + p[3] + p[6];
            s1 += p[1] + p[4] + p[7];
            s2 += p[2] + p[5] + p[8];
        }
        sm_m[w] = (s0 + s1 + s2) * (1.0f / (A_ * C_));
    }
    __syncthreads();

    // phase 2: write 4096 float4s = out[b,h,:,:]
    float4* orow = out + (size_t)(b * H_ + h) * (W_ * F_ / 4);
#pragma unroll
    for (int k = 0; k < 16; k++) {
        int idx = k * 256 + tid;         // 0..4095
        int w  = idx >> 4;
        int f4 = idx & 15;
        float mv = sm_m[w];
        float4 sc = sm_s[f4];
        float4 o;
        o.x = mv * sc.x;
        o.y = mv * sc.y;
        o.z = mv * sc.z;
        o.w = mv * sc.w;
        orow[idx] = o;
    }
}

extern "C" void kernel_launch(void* const* d_in, const int* in_sizes, int n_in,
                              void* d_out, int out_size) {
    const float* lfi = (const float*)d_in[0];   // [4,9,256,256,9]
    const float* fm  = (const float*)d_in[1];   // [4,256,256,64]
    float4* out = (float4*)d_out;               // [4,256,256,64]

    colmean_fmaps_kernel<<<B_ * W_, 256>>>(fm);   // B: one block per (b,w)
    normalize_kernel<<<B_ * F_, 256>>>();         // C: one block per (b,f)
    fused_m_out_kernel<<<B_ * H_, 256>>>(lfi, out); // A+D fused: block per (b,h)
}